// round 14
// baseline (speedup 1.0000x reference)
#include <cuda_runtime.h>

// XrayTransforms: standardize -> soft-hist equalize -> 2x bilinear (=2x2 avg) -> normalize
// x: (2,1,512,512) f32, out: (2,1,256,256) f32
//
// Round 14: eq-table stored as (value, delta) float2 pairs @4096 entries;
// k_out does 1 LDS.64 per pixel; input loads hoisted above table staging.

#define NB 256
#define HW 512
#define NPIX (HW*HW)            // 262144 per batch
#define SUBN 2048
#define SUBSCALE 2040.0f        // 255*8 sub-bins across [0,1]
#define BETA 1.2014610918e-3f   // A / 2040^2, A = 5000
#define RSTEP 0.08539095f       // exp(-2048*BETA): step-32 ratio multiplier
#define TABN 4096
#define NMM 128                 // minmax blocks
#define RADIUS 12
#define TWO_A_D  39.21568627450980f   // 2*A*Delta (Delta = 1/255)
#define A_D2     0.07689350249903883f // A*Delta^2
#define RATIO_C  0.85745500f          // exp(-2*A*Delta^2)
#define INV255   (1.0f/255.0f)
#define LPAD 112                // left pad (need 105)
#define PWIN 2304               // 112 + 2048 + 144
#define PAD (NB + 2*RADIUS)     // 280

__device__ float g_pmin[NMM];
__device__ float g_pmax[NMM];
__device__ float g_scale[2];            // [0]=min, [1]=1/(max-min+1e-6)
__device__ float g_mom[2][SUBN];        // fine hist (atomic-accumulated)
__device__ float g_eqtab[2][TABN + 4];  // +guard

__global__ void k_minmax(const float* __restrict__ x) {
    __shared__ float smn[256], smx[256];
    // zero g_mom: 128 blocks x 32 elements
    if (threadIdx.x < 32)
        ((float*)g_mom)[blockIdx.x * 32 + threadIdx.x] = 0.0f;

    const float4* x4 = (const float4*)x;
    int base = blockIdx.x * 1024 + threadIdx.x;     // 131072 float4 / 128 blocks
    float mn = 1e30f, mx = -1e30f;
    #pragma unroll
    for (int q = 0; q < 4; q++) {
        float4 v = x4[base + q * 256];
        mn = fminf(mn, fminf(fminf(v.x, v.y), fminf(v.z, v.w)));
        mx = fmaxf(mx, fmaxf(fmaxf(v.x, v.y), fmaxf(v.z, v.w)));
    }
    smn[threadIdx.x] = mn; smx[threadIdx.x] = mx;
    __syncthreads();
    for (int o = 128; o; o >>= 1) {
        if (threadIdx.x < o) {
            smn[threadIdx.x] = fminf(smn[threadIdx.x], smn[threadIdx.x + o]);
            smx[threadIdx.x] = fmaxf(smx[threadIdx.x], smx[threadIdx.x + o]);
        }
        __syncthreads();
    }
    if (threadIdx.x == 0) { g_pmin[blockIdx.x] = smn[0]; g_pmax[blockIdx.x] = smx[0]; }
}

// grid (64,2) x 512: 8 px/thread; 1 smem atomic per px; atomic flush to g_mom.
__global__ void k_hist(const float* __restrict__ x) {
    __shared__ float sh[SUBN];                 // 8KB
    __shared__ float smm[128];
    const int t = threadIdx.x;
    if (t < 128) smm[t] = g_pmin[t];
    __syncthreads();
    for (int o = 64; o; o >>= 1) { if (t < o) smm[t] = fminf(smm[t], smm[t + o]); __syncthreads(); }
    const float mn = smm[0];
    __syncthreads();
    if (t < 128) smm[t] = g_pmax[t];
    __syncthreads();
    for (int o = 64; o; o >>= 1) { if (t < o) smm[t] = fmaxf(smm[t], smm[t + o]); __syncthreads(); }
    const float inv = 1.0f / (smm[0] - mn + 1e-6f);
    if (blockIdx.x == 0 && blockIdx.y == 0 && t == 0) { g_scale[0] = mn; g_scale[1] = inv; }

    for (int i = t; i < SUBN; i += 512) sh[i] = 0.0f;
    __syncthreads();

    const int b = blockIdx.y;
    const float4* xb = (const float4*)(x + b * NPIX) + blockIdx.x * 1024;
    #pragma unroll
    for (int q = 0; q < 2; q++) {
        float4 p4 = xb[q * 512 + t];
        float vv[4] = {p4.x, p4.y, p4.z, p4.w};
        #pragma unroll
        for (int qq = 0; qq < 4; qq++) {
            float v = (vv[qq] - mn) * inv;
            int i = __float2int_rn(v * SUBSCALE);
            atomicAdd(&sh[i], 1.0f);
        }
    }
    __syncthreads();
    // counts are exact integers in f32 -> order-independent, deterministic
    float* dst = g_mom[b];
    for (int i = t; i < SUBN; i += 512) {
        float v = sh[i];
        if (v != 0.0f) atomicAdd(&dst[i], v);
    }
}

// grid (8,2) x 512: stage padded fine hist, conv all 256 bins (7 taps/lane),
// scan -> padded cdfn, 512 table entries per block (TABN=4096).
__global__ void k_convtable() {
    __shared__ float win[PWIN];
    __shared__ float SC[NB];
    __shared__ float CP[PAD];
    __shared__ float MP[PAD];
    const int b = blockIdx.y;
    const int t = threadIdx.x;          // 512 threads = 16 warps
    const int wid = t >> 5;
    const int lane = t & 31;

    for (int i = t; i < PWIN; i += 512) {
        int gi = i - LPAD;
        win[i] = (gi >= 0 && gi < SUBN) ? g_mom[b][gi] : 0.0f;
    }
    if (t < PAD) { CP[t] = 0.0f; MP[t] = 0.0f; }
    __syncthreads();

    #pragma unroll
    for (int jj = 0; jj < 16; jj++) {
        const int j = wid * 16 + jj;                 // bin 0..255
        float fm = (float)(lane - 105);
        float w = __expf(-BETA * fm * fm);
        float r = __expf(-BETA * (64.0f * fm + 1024.0f));
        const float* p = win + LPAD + 8 * j + (lane - 105);
        float h = 0.0f;
        #pragma unroll
        for (int it = 0; it < 7; it++) {
            h += w * p[it * 32];
            w *= r;
            r *= RSTEP;
        }
        #pragma unroll
        for (int o = 16; o; o >>= 1) h += __shfl_xor_sync(0xFFFFFFFFu, h, o);
        if (lane == 0) SC[j] = h;
    }
    __syncthreads();

    #pragma unroll
    for (int o = 1; o < NB; o <<= 1) {
        float add = (t < NB && t >= o) ? SC[t - o] : 0.0f;
        __syncthreads();
        if (t < NB) SC[t] += add;
        __syncthreads();
    }
    if (t < NB) {
        float total = SC[NB - 1];
        float invS  = 1.0f / (total + 1e-10f);
        float cdf   = SC[t] * invS;
        float cdf0  = SC[0] * invS;
        CP[t + RADIUS] = (cdf - cdf0) / (1.0f - cdf0 + 1e-10f);
        MP[t + RADIUS] = 1.0f;
    }
    __syncthreads();

    int p = blockIdx.x * 512 + t;       // 0..TABN-1
    float v = (float)p * (1.0f / (float)(TABN - 1));
    int k = __float2int_rn(v * 255.0f);
    int jlo = k - RADIUS;
    float d0 = v - (float)jlo * INV255;
    float w = __expf(-5000.0f * d0 * d0);
    float r = __expf(TWO_A_D * d0 - A_D2);
    const float* cpp = CP + jlo + RADIUS;
    const float* mpp = MP + jlo + RADIUS;
    float num = 0.0f, den = 0.0f;
    #pragma unroll
    for (int st = 0; st < 2 * RADIUS + 1; st++) {
        num = fmaf(w, cpp[st], num);
        den = fmaf(w, mpp[st], den);
        w *= r;
        r *= RATIO_C;
    }
    float e = num / (den + 1e-10f);
    g_eqtab[b][p] = e;
    if (p == TABN - 1) g_eqtab[b][TABN] = e;   // guard duplicate (delta -> 0)
}

__device__ __forceinline__ float eq_lerp2(float xraw, float mn, float inv,
                                          const float2* __restrict__ tb) {
    float v = (xraw - mn) * inv;
    float t = v * (float)(TABN - 1);
    int i0 = (int)t;
    float f = t - (float)i0;
    float2 p = tb[i0];
    return fmaf(f, p.y, p.x);
}

// 128 blocks x 512 threads; (value,delta) table in smem; 2 out px/thread.
__global__ void __launch_bounds__(512)
k_out(const float* __restrict__ x, float* __restrict__ out) {
    __shared__ float2 tab2[TABN];       // 32KB
    const int t = threadIdx.x;
    const int b = blockIdx.x >> 6;      // 64 blocks per batch
    const int sl = blockIdx.x & 63;

    // hoist input loads above staging (independent of smem)
    int local = 2 * t;                   // 0..1022
    int oy = sl * 4 + (local >> 8);
    int ox = local & 255;                // even
    const float* base = x + b * NPIX;
    float4 r0 = *(const float4*)(base + (2 * oy)     * HW + 2 * ox);
    float4 r1 = *(const float4*)(base + (2 * oy + 1) * HW + 2 * ox);

    // stage table as (value, delta): 8 entries per thread
    {
        const float* src = g_eqtab[b];
        float4 a0 = *(const float4*)(src + 8 * t);
        float4 a1 = *(const float4*)(src + 8 * t + 4);
        float nxt = src[8 * t + 8];      // guard entry exists at TABN
        float2* d = tab2 + 8 * t;
        d[0] = make_float2(a0.x, a0.y - a0.x);
        d[1] = make_float2(a0.y, a0.z - a0.y);
        d[2] = make_float2(a0.z, a0.w - a0.z);
        d[3] = make_float2(a0.w, a1.x - a0.w);
        d[4] = make_float2(a1.x, a1.y - a1.x);
        d[5] = make_float2(a1.y, a1.z - a1.y);
        d[6] = make_float2(a1.z, a1.w - a1.z);
        d[7] = make_float2(a1.w, nxt  - a1.w);
    }
    __syncthreads();

    const float mn  = g_scale[0];
    const float inv = g_scale[1];

    float e0 = eq_lerp2(r0.x, mn, inv, tab2) + eq_lerp2(r0.y, mn, inv, tab2)
             + eq_lerp2(r1.x, mn, inv, tab2) + eq_lerp2(r1.y, mn, inv, tab2);
    float e1 = eq_lerp2(r0.z, mn, inv, tab2) + eq_lerp2(r0.w, mn, inv, tab2)
             + eq_lerp2(r1.z, mn, inv, tab2) + eq_lerp2(r1.w, mn, inv, tab2);

    float2 o2;
    o2.x = (0.25f * e0 - 0.15f) / 0.1f;
    o2.y = (0.25f * e1 - 0.15f) / 0.1f;
    *(float2*)(out + b * 65536 + oy * 256 + ox) = o2;
}

extern "C" void kernel_launch(void* const* d_in, const int* in_sizes, int n_in,
                              void* d_out, int out_size) {
    const float* x = (const float*)d_in[0];
    float* out = (float*)d_out;
    k_minmax<<<NMM, 256>>>(x);
    k_hist<<<dim3(64, 2), 512>>>(x);
    k_convtable<<<dim3(8, 2), 512>>>();
    k_out<<<128, 512>>>(x, out);
}

// round 15
// speedup vs baseline: 1.0260x; 1.0260x over previous
#include <cuda_runtime.h>

// XrayTransforms: standardize -> soft-hist equalize -> 2x bilinear (=2x2 avg) -> normalize
// x: (2,1,512,512) f32, out: (2,1,256,256) f32
//
// Round 15: plain-value eq table @ TABN=4096 (16KB smem stage, +guard);
// k_out at 256 blocks x 256 threads (2 blocks/SM overlap). Rest = round 12/13.

#define NB 256
#define HW 512
#define NPIX (HW*HW)            // 262144 per batch
#define SUBN 2048
#define SUBSCALE 2040.0f        // 255*8 sub-bins across [0,1]
#define BETA 1.2014610918e-3f   // A / 2040^2, A = 5000
#define RSTEP 0.08539095f       // exp(-2048*BETA): step-32 ratio multiplier
#define TABN 4096
#define NMM 128                 // minmax blocks
#define RADIUS 12
#define TWO_A_D  39.21568627450980f   // 2*A*Delta (Delta = 1/255)
#define A_D2     0.07689350249903883f // A*Delta^2
#define RATIO_C  0.85745500f          // exp(-2*A*Delta^2)
#define INV255   (1.0f/255.0f)
#define LPAD 112                // left pad (need 105)
#define PWIN 2304               // 112 + 2048 + 144
#define PAD (NB + 2*RADIUS)     // 280

__device__ float g_pmin[NMM];
__device__ float g_pmax[NMM];
__device__ float g_scale[2];            // [0]=min, [1]=1/(max-min+1e-6)
__device__ float g_mom[2][SUBN];        // fine hist (atomic-accumulated)
__device__ float g_eqtab[2][TABN + 4];  // +guard

__global__ void k_minmax(const float* __restrict__ x) {
    __shared__ float smn[256], smx[256];
    // zero g_mom: 128 blocks x 32 elements
    if (threadIdx.x < 32)
        ((float*)g_mom)[blockIdx.x * 32 + threadIdx.x] = 0.0f;

    const float4* x4 = (const float4*)x;
    int base = blockIdx.x * 1024 + threadIdx.x;     // 131072 float4 / 128 blocks
    float mn = 1e30f, mx = -1e30f;
    #pragma unroll
    for (int q = 0; q < 4; q++) {
        float4 v = x4[base + q * 256];
        mn = fminf(mn, fminf(fminf(v.x, v.y), fminf(v.z, v.w)));
        mx = fmaxf(mx, fmaxf(fmaxf(v.x, v.y), fmaxf(v.z, v.w)));
    }
    smn[threadIdx.x] = mn; smx[threadIdx.x] = mx;
    __syncthreads();
    for (int o = 128; o; o >>= 1) {
        if (threadIdx.x < o) {
            smn[threadIdx.x] = fminf(smn[threadIdx.x], smn[threadIdx.x + o]);
            smx[threadIdx.x] = fmaxf(smx[threadIdx.x], smx[threadIdx.x + o]);
        }
        __syncthreads();
    }
    if (threadIdx.x == 0) { g_pmin[blockIdx.x] = smn[0]; g_pmax[blockIdx.x] = smx[0]; }
}

// grid (64,2) x 512: 8 px/thread; 1 smem atomic per px; atomic flush to g_mom.
__global__ void k_hist(const float* __restrict__ x) {
    __shared__ float sh[SUBN];                 // 8KB
    __shared__ float smm[128];
    const int t = threadIdx.x;
    if (t < 128) smm[t] = g_pmin[t];
    __syncthreads();
    for (int o = 64; o; o >>= 1) { if (t < o) smm[t] = fminf(smm[t], smm[t + o]); __syncthreads(); }
    const float mn = smm[0];
    __syncthreads();
    if (t < 128) smm[t] = g_pmax[t];
    __syncthreads();
    for (int o = 64; o; o >>= 1) { if (t < o) smm[t] = fmaxf(smm[t], smm[t + o]); __syncthreads(); }
    const float inv = 1.0f / (smm[0] - mn + 1e-6f);
    if (blockIdx.x == 0 && blockIdx.y == 0 && t == 0) { g_scale[0] = mn; g_scale[1] = inv; }

    for (int i = t; i < SUBN; i += 512) sh[i] = 0.0f;
    __syncthreads();

    const int b = blockIdx.y;
    const float4* xb = (const float4*)(x + b * NPIX) + blockIdx.x * 1024;
    #pragma unroll
    for (int q = 0; q < 2; q++) {
        float4 p4 = xb[q * 512 + t];
        float vv[4] = {p4.x, p4.y, p4.z, p4.w};
        #pragma unroll
        for (int qq = 0; qq < 4; qq++) {
            float v = (vv[qq] - mn) * inv;
            int i = __float2int_rn(v * SUBSCALE);
            atomicAdd(&sh[i], 1.0f);
        }
    }
    __syncthreads();
    // counts are exact integers in f32 -> order-independent, deterministic
    float* dst = g_mom[b];
    for (int i = t; i < SUBN; i += 512) {
        float v = sh[i];
        if (v != 0.0f) atomicAdd(&dst[i], v);
    }
}

// grid (8,2) x 512: stage padded fine hist, conv all 256 bins (7 taps/lane),
// scan -> padded cdfn, 512 table entries per block (TABN=4096).
__global__ void k_convtable() {
    __shared__ float win[PWIN];
    __shared__ float SC[NB];
    __shared__ float CP[PAD];
    __shared__ float MP[PAD];
    const int b = blockIdx.y;
    const int t = threadIdx.x;          // 512 threads = 16 warps
    const int wid = t >> 5;
    const int lane = t & 31;

    for (int i = t; i < PWIN; i += 512) {
        int gi = i - LPAD;
        win[i] = (gi >= 0 && gi < SUBN) ? g_mom[b][gi] : 0.0f;
    }
    if (t < PAD) { CP[t] = 0.0f; MP[t] = 0.0f; }
    __syncthreads();

    #pragma unroll
    for (int jj = 0; jj < 16; jj++) {
        const int j = wid * 16 + jj;                 // bin 0..255
        float fm = (float)(lane - 105);
        float w = __expf(-BETA * fm * fm);
        float r = __expf(-BETA * (64.0f * fm + 1024.0f));
        const float* p = win + LPAD + 8 * j + (lane - 105);
        float h = 0.0f;
        #pragma unroll
        for (int it = 0; it < 7; it++) {
            h += w * p[it * 32];
            w *= r;
            r *= RSTEP;
        }
        #pragma unroll
        for (int o = 16; o; o >>= 1) h += __shfl_xor_sync(0xFFFFFFFFu, h, o);
        if (lane == 0) SC[j] = h;
    }
    __syncthreads();

    #pragma unroll
    for (int o = 1; o < NB; o <<= 1) {
        float add = (t < NB && t >= o) ? SC[t - o] : 0.0f;
        __syncthreads();
        if (t < NB) SC[t] += add;
        __syncthreads();
    }
    if (t < NB) {
        float total = SC[NB - 1];
        float invS  = 1.0f / (total + 1e-10f);
        float cdf   = SC[t] * invS;
        float cdf0  = SC[0] * invS;
        CP[t + RADIUS] = (cdf - cdf0) / (1.0f - cdf0 + 1e-10f);
        MP[t + RADIUS] = 1.0f;
    }
    __syncthreads();

    int p = blockIdx.x * 512 + t;       // 0..TABN-1
    float v = (float)p * (1.0f / (float)(TABN - 1));
    int k = __float2int_rn(v * 255.0f);
    int jlo = k - RADIUS;
    float d0 = v - (float)jlo * INV255;
    float w = __expf(-5000.0f * d0 * d0);
    float r = __expf(TWO_A_D * d0 - A_D2);
    const float* cpp = CP + jlo + RADIUS;
    const float* mpp = MP + jlo + RADIUS;
    float num = 0.0f, den = 0.0f;
    #pragma unroll
    for (int st = 0; st < 2 * RADIUS + 1; st++) {
        num = fmaf(w, cpp[st], num);
        den = fmaf(w, mpp[st], den);
        w *= r;
        r *= RATIO_C;
    }
    float e = num / (den + 1e-10f);
    g_eqtab[b][p] = e;
    if (p == TABN - 1) g_eqtab[b][TABN] = e;   // guard duplicate
}

__device__ __forceinline__ float eq_lerp_s(float xraw, float mn, float inv,
                                           const float* __restrict__ tb) {
    float v = (xraw - mn) * inv;
    float t = v * (float)(TABN - 1);
    int i0 = (int)t;
    float f = t - (float)i0;
    float e0 = tb[i0];
    float e1 = tb[i0 + 1];
    return fmaf(f, e1 - e0, e0);
}

// 256 blocks x 256 threads (2 blocks/SM); 16KB table in smem; 2 out px/thread.
__global__ void __launch_bounds__(256)
k_out(const float* __restrict__ x, float* __restrict__ out) {
    __shared__ float tab[TABN + 1];     // 16.4KB
    const int t = threadIdx.x;
    const int b = blockIdx.x >> 7;      // 128 blocks per batch
    const int sl = blockIdx.x & 127;

    // hoist input loads above staging (independent of smem)
    int local = 2 * t;                   // 0..510
    int oy = sl * 2 + (local >> 8);      // block covers 2 output rows
    int ox = local & 255;                // even
    const float* base = x + b * NPIX;
    float4 r0 = *(const float4*)(base + (2 * oy)     * HW + 2 * ox);
    float4 r1 = *(const float4*)(base + (2 * oy + 1) * HW + 2 * ox);

    {
        const float4* src = (const float4*)g_eqtab[b];
        float4* dst4 = (float4*)tab;
        #pragma unroll
        for (int q = 0; q < 4; q++) dst4[q * 256 + t] = src[q * 256 + t];
        if (t == 0) tab[TABN] = tab[TABN - 1];   // guard for v == 1.0
    }
    __syncthreads();

    const float mn  = g_scale[0];
    const float inv = g_scale[1];

    float e0 = eq_lerp_s(r0.x, mn, inv, tab) + eq_lerp_s(r0.y, mn, inv, tab)
             + eq_lerp_s(r1.x, mn, inv, tab) + eq_lerp_s(r1.y, mn, inv, tab);
    float e1 = eq_lerp_s(r0.z, mn, inv, tab) + eq_lerp_s(r0.w, mn, inv, tab)
             + eq_lerp_s(r1.z, mn, inv, tab) + eq_lerp_s(r1.w, mn, inv, tab);

    float2 o2;
    o2.x = (0.25f * e0 - 0.15f) / 0.1f;
    o2.y = (0.25f * e1 - 0.15f) / 0.1f;
    *(float2*)(out + b * 65536 + oy * 256 + ox) = o2;
}

extern "C" void kernel_launch(void* const* d_in, const int* in_sizes, int n_in,
                              void* d_out, int out_size) {
    const float* x = (const float*)d_in[0];
    float* out = (float*)d_out;
    k_minmax<<<NMM, 256>>>(x);
    k_hist<<<dim3(64, 2), 512>>>(x);
    k_convtable<<<dim3(8, 2), 512>>>();
    k_out<<<256, 256>>>(x, out);
}